// round 2
// baseline (speedup 1.0000x reference)
#include <cuda_runtime.h>
#include <cuda_bf16.h>

// Problem constants
#define BATCH   128
#define T_STEPS 256
#define IN_F    1024
#define OUT_C   512
#define M_TOTAL (BATCH * T_STEPS)   // 32768

// SNN hyperparameters
#define V_TH      0.4f
#define V_RESET   0.0f
#define LEAK      0.01f
#define REFR_LEAK 0.01f
#define REFR_POT  0.0f
#define STD_POT   0.0f
#define REFRAC    2.0f

// 64 MB scratch for I = x @ W, laid out [B*T, C] row-major (row = b*T + t)
__device__ float g_I[(size_t)M_TOTAL * OUT_C];

// ---------------------------------------------------------------------------
// SGEMM: C[M,N] = A[M,K] @ B[K,N], fp32.
// M=32768, N=512, K=1024. BM=128, BN=128, BK=8, 256 threads, 8x8 microtile.
// ---------------------------------------------------------------------------
#define BM 128
#define BN 128
#define BK 8
#define TM 8
#define TN 8

__global__ __launch_bounds__(256, 2)
void snn_gemm_kernel(const float* __restrict__ A,
                     const float* __restrict__ B) {
    __shared__ float As[BK][BM];   // A tile, transposed: As[k][m]
    __shared__ float Bs[BK][BN];   // B tile: Bs[k][n]

    const int tid = threadIdx.x;
    const int blockRow = blockIdx.y;   // 0..255
    const int blockCol = blockIdx.x;   // 0..3

    // microtile coordinates: 16 x 16 thread grid
    const int tCol = tid % (BN / TN);  // 0..15
    const int tRow = tid / (BN / TN);  // 0..15

    // A global-load mapping: each thread loads one float4 per BK-slab
    const int aRow = tid >> 1;          // 0..127
    const int aCol = (tid & 1) * 4;     // 0 or 4
    // B global-load mapping
    const int bRow = tid >> 5;          // 0..7
    const int bCol = (tid & 31) * 4;    // 0..124

    const float* Ablk = A + (size_t)blockRow * BM * IN_F;
    const float* Bblk = B + blockCol * BN;
    float* Cblk = g_I + (size_t)blockRow * BM * OUT_C + blockCol * BN;

    float acc[TM][TN];
    #pragma unroll
    for (int i = 0; i < TM; i++)
        #pragma unroll
        for (int j = 0; j < TN; j++)
            acc[i][j] = 0.0f;

    float ra[TM], rb[TN];

    for (int k0 = 0; k0 < IN_F; k0 += BK) {
        // load A slab (128 x 8) transposed into smem
        float4 a4 = *(const float4*)(Ablk + (size_t)aRow * IN_F + k0 + aCol);
        As[aCol + 0][aRow] = a4.x;
        As[aCol + 1][aRow] = a4.y;
        As[aCol + 2][aRow] = a4.z;
        As[aCol + 3][aRow] = a4.w;
        // load B slab (8 x 128)
        float4 b4 = *(const float4*)(Bblk + (size_t)(k0 + bRow) * OUT_C + bCol);
        *(float4*)&Bs[bRow][bCol] = b4;
        __syncthreads();

        #pragma unroll
        for (int k = 0; k < BK; k++) {
            #pragma unroll
            for (int i = 0; i < TM; i++) ra[i] = As[k][tRow * TM + i];
            #pragma unroll
            for (int j = 0; j < TN; j++) rb[j] = Bs[k][tCol * TN + j];
            #pragma unroll
            for (int i = 0; i < TM; i++)
                #pragma unroll
                for (int j = 0; j < TN; j++)
                    acc[i][j] = fmaf(ra[i], rb[j], acc[i][j]);
        }
        __syncthreads();
    }

    #pragma unroll
    for (int i = 0; i < TM; i++) {
        #pragma unroll
        for (int j = 0; j < TN; j += 4) {
            float4 v = make_float4(acc[i][j], acc[i][j + 1],
                                   acc[i][j + 2], acc[i][j + 3]);
            *(float4*)(Cblk + (size_t)(tRow * TM + i) * OUT_C + tCol * TN + j) = v;
        }
    }
}

// ---------------------------------------------------------------------------
// Per-neuron sequential scan over T. One thread per (b, c) neuron.
// Loads of I are independent of the recurrent state -> unroll for MLP.
// Faithful replication of reference step semantics:
//   masks m_std/m_abs/m_rel are computed from the OLD mode, so the three
//   branches are mutually exclusive per step (if/else chain is exact).
// ---------------------------------------------------------------------------
__global__ __launch_bounds__(256)
void snn_scan_kernel(float* __restrict__ out) {
    const int idx = blockIdx.x * blockDim.x + threadIdx.x;  // 0..65535
    const int b = idx >> 9;        // / OUT_C
    const int c = idx & (OUT_C - 1);

    const float* Ip = g_I + ((size_t)b * T_STEPS) * OUT_C + c;

    float V = 0.0f, refr = 0.0f, sc = 0.0f;
    int mode = 0;

    #pragma unroll 8
    for (int t = 0; t < T_STEPS; t++) {
        const float I = Ip[(size_t)t * OUT_C];
        if (mode == 0) {
            // standard: integrate, leak, floor at STD_POT, spike
            V = V + I - LEAK;
            if (V < STD_POT) V = STD_POT;
            if (V - V_TH > 0.0f) {
                sc += 1.0f;
                V = V_RESET;
                refr = REFRAC;
                mode = 1;
            }
        } else if (mode == 1) {
            // absolute refractory: count down
            refr = fmaxf(refr - 1.0f, 0.0f);
            if (refr <= 0.0f) mode = 2;
            if (V < REFR_POT) V = REFR_POT;
        } else {
            // relative refractory: recover toward standard
            V += REFR_LEAK;
            if (V < REFR_POT) V = REFR_POT;
            if (V > STD_POT) mode = 0;
        }
    }

    out[idx] = sc;
}

// ---------------------------------------------------------------------------
extern "C" void kernel_launch(void* const* d_in, const int* in_sizes, int n_in,
                              void* d_out, int out_size) {
    const float* x_seq = (const float*)d_in[0];  // [B, T, F] == [M_TOTAL, IN_F]
    const float* W     = (const float*)d_in[1];  // [IN_F, OUT_C]
    float* out = (float*)d_out;                  // [B, C] spike counts

    dim3 gemmGrid(OUT_C / BN, M_TOTAL / BM);     // (4, 256)
    snn_gemm_kernel<<<gemmGrid, 256>>>(x_seq, W);

    snn_scan_kernel<<<(BATCH * OUT_C) / 256, 256>>>(out);
}

// round 4
// speedup vs baseline: 2.5106x; 2.5106x over previous
#include <cuda_runtime.h>
#include <cuda_bf16.h>
#include <cstdint>

// ---------------------------------------------------------------------------
// Problem constants
// ---------------------------------------------------------------------------
#define BATCH   128
#define T_STEPS 256
#define IN_F    1024
#define OUT_C   512
#define M_TOTAL (BATCH * T_STEPS)   // 32768
#define KPRIME  3072                // 3 * IN_F (hi*hi, hi*lo, lo*hi)
#define NKT     96                  // KPRIME / 32

// SNN hyperparameters
#define V_TH      0.4f
#define LEAK      0.01f
#define REFR_LEAK 0.01f
#define REFRAC    2.0f

// ---------------------------------------------------------------------------
// Device scratch (static __device__: allocation-guard safe)
// A2 : [32768][3072] bf16 row-major = 192 MB   ([hi | hi | lo] along k')
// Bt : [512][3072]   bf16 row-major = 3 MB     ([hi | lo | hi] along k')
// ---------------------------------------------------------------------------
__device__ __align__(128) unsigned char g_A2[(size_t)M_TOTAL * KPRIME * 2];
__device__ __align__(128) unsigned char g_Bt[(size_t)OUT_C * KPRIME * 2];
__device__ float g_I[(size_t)M_TOTAL * OUT_C];   // 64 MB

// ---------------------------------------------------------------------------
// Helpers (base sm_80/sm_90 ISA only — NO 'a'-gated instructions)
// ---------------------------------------------------------------------------
__device__ __forceinline__ uint32_t smem_u32(const void* p) {
    uint32_t a;
    asm("{ .reg .u64 t; cvta.to.shared.u64 t, %1; cvt.u32.u64 %0, t; }"
        : "=r"(a) : "l"(p));
    return a;
}

__device__ __forceinline__ void cp_async16(uint32_t dst, const void* src) {
    asm volatile("cp.async.cg.shared.global [%0], [%1], 16;"
                 :: "r"(dst), "l"(src) : "memory");
}

#define CP_COMMIT() asm volatile("cp.async.commit_group;" ::: "memory")
#define CP_WAIT1()  asm volatile("cp.async.wait_group 1;" ::: "memory")

__device__ __forceinline__ void ldmatrix_x4(uint32_t* r, uint32_t addr) {
    asm volatile("ldmatrix.sync.aligned.m8n8.x4.shared.b16 {%0,%1,%2,%3}, [%4];"
                 : "=r"(r[0]), "=r"(r[1]), "=r"(r[2]), "=r"(r[3]) : "r"(addr));
}

__device__ __forceinline__ void mma16816(float* d, const uint32_t* a,
                                         uint32_t b0, uint32_t b1) {
    asm volatile(
        "mma.sync.aligned.m16n8k16.row.col.f32.bf16.bf16.f32 "
        "{%0,%1,%2,%3}, {%4,%5,%6,%7}, {%8,%9}, {%0,%1,%2,%3};"
        : "+f"(d[0]), "+f"(d[1]), "+f"(d[2]), "+f"(d[3])
        : "r"(a[0]), "r"(a[1]), "r"(a[2]), "r"(a[3]), "r"(b0), "r"(b1));
}

// Swizzled smem byte offset for a 128-row x 64-byte tile.
// (row, chunk16) -> line = row/2 (128B lines), chunk8 = (row&1)*4 + chunk,
// phys = line*128 + (chunk8 ^ (line&7))*16.  ldmatrix conflict-free.
__device__ __forceinline__ uint32_t tile_off(int r, int c) {
    int line = r >> 1;
    int ch8 = (((r & 1) * 4 + c) ^ (line & 7));
    return (uint32_t)(line * 128 + ch8 * 16);
}

// ---------------------------------------------------------------------------
// conv_A: x fp32 [32768][1024] -> A2 bf16 [m][3072] = [hi | hi | lo]
// ---------------------------------------------------------------------------
__global__ __launch_bounds__(256)
void conv_A_kernel(const float4* __restrict__ x) {
    const uint32_t i = blockIdx.x * 256 + threadIdx.x;   // 0 .. 8388607
    const uint32_t m  = i >> 8;
    const uint32_t ko = (i & 255) * 4;
    float4 v = x[i];

    __nv_bfloat16 h0 = __float2bfloat16_rn(v.x);
    __nv_bfloat16 h1 = __float2bfloat16_rn(v.y);
    __nv_bfloat16 h2 = __float2bfloat16_rn(v.z);
    __nv_bfloat16 h3 = __float2bfloat16_rn(v.w);
    __nv_bfloat16 l0 = __float2bfloat16_rn(v.x - __bfloat162float(h0));
    __nv_bfloat16 l1 = __float2bfloat16_rn(v.y - __bfloat162float(h1));
    __nv_bfloat16 l2 = __float2bfloat16_rn(v.z - __bfloat162float(h2));
    __nv_bfloat16 l3 = __float2bfloat16_rn(v.w - __bfloat162float(h3));

    uint2 ph, pl;
    ph.x = ((uint32_t)__bfloat16_as_ushort(h1) << 16) | __bfloat16_as_ushort(h0);
    ph.y = ((uint32_t)__bfloat16_as_ushort(h3) << 16) | __bfloat16_as_ushort(h2);
    pl.x = ((uint32_t)__bfloat16_as_ushort(l1) << 16) | __bfloat16_as_ushort(l0);
    pl.y = ((uint32_t)__bfloat16_as_ushort(l3) << 16) | __bfloat16_as_ushort(l2);

    unsigned char* row = g_A2 + (size_t)m * (KPRIME * 2);
    *(uint2*)(row + (ko) * 2)                = ph;
    *(uint2*)(row + (IN_F + ko) * 2)         = ph;
    *(uint2*)(row + (2 * IN_F + ko) * 2)     = pl;
}

// ---------------------------------------------------------------------------
// conv_B: W fp32 [1024 k][512 n] -> Bt bf16 [n][3072] = [hi | lo | hi]
// Thread mapping: k fastest for coalesced 2B writes along k.
// ---------------------------------------------------------------------------
__global__ __launch_bounds__(256)
void conv_B_kernel(const float* __restrict__ W) {
    const uint32_t i = blockIdx.x * 256 + threadIdx.x;   // 0 .. 524287
    const uint32_t k = i & 1023;
    const uint32_t n = i >> 10;
    float w = W[(size_t)k * OUT_C + n];
    __nv_bfloat16 hi = __float2bfloat16_rn(w);
    __nv_bfloat16 lo = __float2bfloat16_rn(w - __bfloat162float(hi));
    unsigned short uhi = __bfloat16_as_ushort(hi);
    unsigned short ulo = __bfloat16_as_ushort(lo);

    unsigned char* row = g_Bt + (size_t)n * (KPRIME * 2);
    *(unsigned short*)(row + (k) * 2)            = uhi;
    *(unsigned short*)(row + (IN_F + k) * 2)     = ulo;
    *(unsigned short*)(row + (2 * IN_F + k) * 2) = uhi;
}

// ---------------------------------------------------------------------------
// GEMM: g_I[32768][512] = A2[32768][3072] x Bt[512][3072]^T  (bf16 -> fp32)
// CTA tile 128x128, BK=32, 8 warps (4x2, warp tile 32x64), mma.sync 16x8x16.
// 3-stage cp.async pipeline, swizzled smem, ldmatrix fragment loads.
// ---------------------------------------------------------------------------
__global__ __launch_bounds__(256, 2)
void snn_gemm_mma() {
    __shared__ __align__(1024) unsigned char smA[3][8192];
    __shared__ __align__(1024) unsigned char smB[3][8192];

    const int tid  = threadIdx.x;
    const int lane = tid & 31;
    const int wid  = tid >> 5;
    const int wm   = wid >> 1;          // 0..3
    const int wn   = wid & 1;           // 0..1
    const int mBase = blockIdx.y * 128;
    const int nBase = blockIdx.x * 128;

    // per-thread load coordinates (2 chunks each for A and B)
    const int r0 = tid >> 2, c0 = tid & 3;          // chunk i = tid
    const int r1 = (tid + 256) >> 2, c1 = tid & 3;  // chunk i = tid + 256
    const uint32_t sA = smem_u32(&smA[0][0]);
    const uint32_t sB = smem_u32(&smB[0][0]);
    const uint32_t offA0 = tile_off(r0, c0), offA1 = tile_off(r1, c1);

    const unsigned char* gA0 = g_A2 + (size_t)(mBase + r0) * (KPRIME * 2);
    const unsigned char* gA1 = g_A2 + (size_t)(mBase + r1) * (KPRIME * 2);
    const unsigned char* gB0 = g_Bt + (size_t)(nBase + r0) * (KPRIME * 2);
    const unsigned char* gB1 = g_Bt + (size_t)(nBase + r1) * (KPRIME * 2);

    auto load_stage = [&](int stg, int kt) {
        const uint32_t kb = (uint32_t)kt * 64;
        cp_async16(sA + stg * 8192 + offA0, gA0 + kb + c0 * 16);
        cp_async16(sA + stg * 8192 + offA1, gA1 + kb + c1 * 16);
        cp_async16(sB + stg * 8192 + offA0, gB0 + kb + c0 * 16);
        cp_async16(sB + stg * 8192 + offA1, gB1 + kb + c1 * 16);
    };

    float acc[2][8][4];
    #pragma unroll
    for (int mf = 0; mf < 2; mf++)
        #pragma unroll
        for (int nf = 0; nf < 8; nf++)
            #pragma unroll
            for (int d = 0; d < 4; d++) acc[mf][nf][d] = 0.0f;

    // ldmatrix per-lane row indices (chunk varies per kstep)
    const int lrow = (lane & 7) + 8 * ((lane >> 3) & 1);
    const int lkc  = lane >> 4;   // 0/1: k-half chunk

    load_stage(0, 0); CP_COMMIT();
    load_stage(1, 1); CP_COMMIT();

    for (int kt = 0; kt < NKT; kt++) {
        CP_WAIT1();
        __syncthreads();
        if (kt + 2 < NKT) load_stage((kt + 2) % 3, kt + 2);
        CP_COMMIT();

        const int stg = kt % 3;
        const uint32_t bA = sA + stg * 8192;
        const uint32_t bB = sB + stg * 8192;
        #pragma unroll
        for (int ks = 0; ks < 2; ks++) {
            const int ch = ks * 2 + lkc;
            uint32_t a[2][4], b[4][4];
            #pragma unroll
            for (int mf = 0; mf < 2; mf++) {
                int r = wm * 32 + mf * 16 + lrow;
                ldmatrix_x4(a[mf], bA + tile_off(r, ch));
            }
            #pragma unroll
            for (int g = 0; g < 4; g++) {
                int r = wn * 64 + g * 16 + lrow;
                ldmatrix_x4(b[g], bB + tile_off(r, ch));
            }
            #pragma unroll
            for (int mf = 0; mf < 2; mf++)
                #pragma unroll
                for (int g = 0; g < 4; g++) {
                    mma16816(acc[mf][2 * g],     a[mf], b[g][0], b[g][2]);
                    mma16816(acc[mf][2 * g + 1], a[mf], b[g][1], b[g][3]);
                }
        }
    }

    // epilogue: write fp32 accumulators to g_I
    #pragma unroll
    for (int mf = 0; mf < 2; mf++) {
        #pragma unroll
        for (int nf = 0; nf < 8; nf++) {
            const int row = mBase + wm * 32 + mf * 16 + (lane >> 2);
            const int col = nBase + wn * 64 + nf * 8 + (lane & 3) * 2;
            float* p0 = g_I + (size_t)row * OUT_C + col;
            float* p1 = p0 + 8 * OUT_C;
            *(float2*)p0 = make_float2(acc[mf][nf][0], acc[mf][nf][1]);
            *(float2*)p1 = make_float2(acc[mf][nf][2], acc[mf][nf][3]);
        }
    }
}

// ---------------------------------------------------------------------------
// Branchless per-neuron scan over T. 8-wide batched loads for MLP.
// Exact replication of reference step semantics (masks from OLD mode).
// ---------------------------------------------------------------------------
__global__ __launch_bounds__(256)
void snn_scan_kernel(float* __restrict__ out) {
    const int idx = blockIdx.x * 256 + threadIdx.x;   // 0..65535
    const float* Ip = g_I + ((size_t)(idx >> 9)) * T_STEPS * OUT_C + (idx & 511);

    float V = 0.0f, refr = 0.0f, sc = 0.0f;
    int mode = 0;

    for (int t0 = 0; t0 < T_STEPS; t0 += 8) {
        float buf[8];
        #pragma unroll
        for (int j = 0; j < 8; j++)
            buf[j] = Ip[(size_t)(t0 + j) * OUT_C];
        #pragma unroll
        for (int j = 0; j < 8; j++) {
            const float I = buf[j];
            const float v_std = fmaxf(V + I - LEAK, 0.0f);       // STD_POT=0
            const bool  fire  = (mode == 0) && (v_std > V_TH);   // strict >
            const float r_abs = fmaxf(refr - 1.0f, 0.0f);
            const bool  done  = (r_abs <= 0.0f);
            const float v_abs = fmaxf(V, 0.0f);                  // REFR_POT=0
            const float v_rel = fmaxf(V + REFR_LEAK, 0.0f);
            const bool  back  = (v_rel > 0.0f);                  // STD_POT=0

            const float Vn = (mode == 0) ? (fire ? 0.0f : v_std)
                           : (mode == 1) ? v_abs : v_rel;
            const float rn = (mode == 0) ? (fire ? REFRAC : refr)
                           : (mode == 1) ? r_abs : refr;
            const int   mn = (mode == 0) ? (fire ? 1 : 0)
                           : (mode == 1) ? (done ? 2 : 1)
                           : (back ? 0 : 2);
            sc += fire ? 1.0f : 0.0f;
            V = Vn; refr = rn; mode = mn;
        }
    }
    out[idx] = sc;
}

// ---------------------------------------------------------------------------
extern "C" void kernel_launch(void* const* d_in, const int* in_sizes, int n_in,
                              void* d_out, int out_size) {
    const float* x_seq = (const float*)d_in[0];  // [B, T, F]
    const float* W     = (const float*)d_in[1];  // [F, C]
    float* out = (float*)d_out;                  // [B, C]

    conv_A_kernel<<<(M_TOTAL * IN_F / 4) / 256, 256>>>((const float4*)x_seq);
    conv_B_kernel<<<(IN_F * OUT_C) / 256, 256>>>(W);

    dim3 gemmGrid(OUT_C / 128, M_TOTAL / 128);   // (4, 256)
    snn_gemm_mma<<<gemmGrid, 256>>>();

    snn_scan_kernel<<<(BATCH * OUT_C) / 256, 256>>>(out);
}